// round 1
// baseline (speedup 1.0000x reference)
#include <cuda_runtime.h>
#include <math.h>

// Problem dims (fixed by the dataset)
#define T_TOK 8192
#define H_DIM 2048
#define I_DIM 1408
#define E_NUM 32

// Scratch for the fused gate/up intermediate h = silu(x@Wg) * (x@Wu), [T, I].
// __device__ global (no allocations allowed anywhere).
__device__ float g_h[(size_t)T_TOK * I_DIM];

// ---------------------------------------------------------------------------
// Kernel 1: fused gate+up.  C_g = X@Wg[e], C_u = X@Wu[e], h = silu(C_g)*C_u
// Block tile: BM=128 (tokens) x BN=64 (I cols), BK=16.  256 threads,
// per-thread 8x4 outputs for EACH of the two matrices (64 fp32 accumulators).
// Expert boundaries are multiples of 256 >= BM, so a tile never crosses one.
// ---------------------------------------------------------------------------
__global__ __launch_bounds__(256, 2)
void gateup_kernel(const float* __restrict__ x,
                   const float* __restrict__ Wg,
                   const float* __restrict__ Wu,
                   const int*   __restrict__ offs)
{
    const int BM = 128, BN = 64, BK = 16;
    __shared__ float As[BK][BM];   // X tile, transposed  (8 KB)
    __shared__ float Bg[BK][BN];   // Wg tile             (4 KB)
    __shared__ float Bu[BK][BN];   // Wu tile             (4 KB)

    const int n0 = blockIdx.x * BN;
    const int m0 = blockIdx.y * BM;

    // Expert lookup: smallest e with offs[e] > m0 (offs are cumulative ends).
    int e = 0;
    while (offs[e] <= m0) e++;

    const float* wg = Wg + (size_t)e * H_DIM * I_DIM;
    const float* wu = Wu + (size_t)e * H_DIM * I_DIM;

    const int tid = threadIdx.x;
    const int tx  = tid & 15;   // N direction: 16 threads * 4 cols = 64
    const int ty  = tid >> 4;   // M direction: 16 threads * 8 rows = 128

    float acc_g[8][4];
    float acc_u[8][4];
    #pragma unroll
    for (int i = 0; i < 8; i++)
        #pragma unroll
        for (int j = 0; j < 4; j++) { acc_g[i][j] = 0.f; acc_u[i][j] = 0.f; }

    for (int k0 = 0; k0 < H_DIM; k0 += BK) {
        // Load X tile: 128 rows x 16 cols = 512 float4, 2 per thread,
        // stored transposed so the compute loop reads As[k][m].
        #pragma unroll
        for (int j = 0; j < 2; j++) {
            int id  = tid + 256 * j;        // 0..511
            int row = id >> 2;              // 0..127
            int kk  = (id & 3) * 4;         // 0,4,8,12
            float4 v = *(const float4*)(x + (size_t)(m0 + row) * H_DIM + k0 + kk);
            As[kk + 0][row] = v.x;
            As[kk + 1][row] = v.y;
            As[kk + 2][row] = v.z;
            As[kk + 3][row] = v.w;
        }
        // Load Wg/Wu tiles: 16 rows x 64 cols = 256 float4 each, 1 per thread.
        {
            int row = tid >> 4;             // 0..15
            int cc  = (tid & 15) * 4;       // 0..60
            *(float4*)&Bg[row][cc] =
                *(const float4*)(wg + (size_t)(k0 + row) * I_DIM + n0 + cc);
            *(float4*)&Bu[row][cc] =
                *(const float4*)(wu + (size_t)(k0 + row) * I_DIM + n0 + cc);
        }
        __syncthreads();

        #pragma unroll
        for (int k = 0; k < BK; k++) {
            float a[8], bg[4], bu[4];
            #pragma unroll
            for (int i = 0; i < 8; i++) a[i] = As[k][ty * 8 + i];
            #pragma unroll
            for (int j = 0; j < 4; j++) { bg[j] = Bg[k][tx * 4 + j];
                                          bu[j] = Bu[k][tx * 4 + j]; }
            #pragma unroll
            for (int i = 0; i < 8; i++)
                #pragma unroll
                for (int j = 0; j < 4; j++) {
                    acc_g[i][j] = fmaf(a[i], bg[j], acc_g[i][j]);
                    acc_u[i][j] = fmaf(a[i], bu[j], acc_u[i][j]);
                }
        }
        __syncthreads();
    }

    // Epilogue: h = silu(g) * u
    #pragma unroll
    for (int i = 0; i < 8; i++) {
        int m = m0 + ty * 8 + i;
        #pragma unroll
        for (int j = 0; j < 4; j++) {
            float g = acc_g[i][j];
            float s = g / (1.0f + __expf(-g));
            g_h[(size_t)m * I_DIM + n0 + tx * 4 + j] = s * acc_u[i][j];
        }
    }
}

// ---------------------------------------------------------------------------
// Kernel 2: down proj.  out = h @ Wd[e],  h:[T,I], Wd[e]:[I,H], out:[T,H]
// Block tile: BM=128 x BN=128, BK=16.  256 threads, per-thread 8x8 outputs.
// ---------------------------------------------------------------------------
__global__ __launch_bounds__(256, 2)
void down_kernel(const float* __restrict__ Wd,
                 const int*   __restrict__ offs,
                 float*       __restrict__ out)
{
    const int BM = 128, BN = 128, BK = 16;
    __shared__ float As[BK][BM];   // h tile, transposed  (8 KB)
    __shared__ float Bs[BK][BN];   // Wd tile             (8 KB)

    const int n0 = blockIdx.x * BN;
    const int m0 = blockIdx.y * BM;

    int e = 0;
    while (offs[e] <= m0) e++;
    const float* wd = Wd + (size_t)e * I_DIM * H_DIM;

    const int tid = threadIdx.x;
    const int tx  = tid & 15;   // N: 16 threads * 8 cols = 128
    const int ty  = tid >> 4;   // M: 16 threads * 8 rows = 128

    float acc[8][8];
    #pragma unroll
    for (int i = 0; i < 8; i++)
        #pragma unroll
        for (int j = 0; j < 8; j++) acc[i][j] = 0.f;

    for (int k0 = 0; k0 < I_DIM; k0 += BK) {
        // h tile: 128 x 16 = 512 float4, 2 per thread, stored transposed.
        #pragma unroll
        for (int j = 0; j < 2; j++) {
            int id  = tid + 256 * j;
            int row = id >> 2;              // 0..127
            int kk  = (id & 3) * 4;         // 0,4,8,12
            float4 v = *(const float4*)(g_h + (size_t)(m0 + row) * I_DIM + k0 + kk);
            As[kk + 0][row] = v.x;
            As[kk + 1][row] = v.y;
            As[kk + 2][row] = v.z;
            As[kk + 3][row] = v.w;
        }
        // Wd tile: 16 rows x 128 cols = 512 float4, 2 per thread.
        #pragma unroll
        for (int j = 0; j < 2; j++) {
            int id  = tid + 256 * j;
            int row = id >> 5;              // 0..15
            int cc  = (id & 31) * 4;        // 0..124
            *(float4*)&Bs[row][cc] =
                *(const float4*)(wd + (size_t)(k0 + row) * H_DIM + n0 + cc);
        }
        __syncthreads();

        #pragma unroll
        for (int k = 0; k < BK; k++) {
            float a[8], b[8];
            #pragma unroll
            for (int i = 0; i < 8; i++) a[i] = As[k][ty * 8 + i];
            #pragma unroll
            for (int j = 0; j < 8; j++) b[j] = Bs[k][tx * 8 + j];
            #pragma unroll
            for (int i = 0; i < 8; i++)
                #pragma unroll
                for (int j = 0; j < 8; j++)
                    acc[i][j] = fmaf(a[i], b[j], acc[i][j]);
        }
        __syncthreads();
    }

    #pragma unroll
    for (int i = 0; i < 8; i++) {
        int m = m0 + ty * 8 + i;
        #pragma unroll
        for (int j = 0; j < 8; j++)
            out[(size_t)m * H_DIM + n0 + tx * 8 + j] = acc[i][j];
    }
}

// ---------------------------------------------------------------------------
extern "C" void kernel_launch(void* const* d_in, const int* in_sizes, int n_in,
                              void* d_out, int out_size)
{
    const float* x    = (const float*)d_in[0];   // [T, H]
    const float* Wg   = (const float*)d_in[1];   // [E, H, I]
    const float* Wu   = (const float*)d_in[2];   // [E, H, I]
    const float* Wd   = (const float*)d_in[3];   // [E, I, H]
    const int*   offs = (const int*)  d_in[4];   // [E] cumulative ends
    float*       out  = (float*)d_out;           // [T, H]

    dim3 grid1(I_DIM / 64, T_TOK / 128);   // (22, 64)
    dim3 grid2(H_DIM / 128, T_TOK / 128);  // (16, 64)

    gateup_kernel<<<grid1, 256>>>(x, Wg, Wu, offs);
    down_kernel<<<grid2, 256>>>(Wd, offs, out);
}

// round 3
// speedup vs baseline: 1.6761x; 1.6761x over previous
#include <cuda_runtime.h>
#include <cuda_bf16.h>
#include <cstdint>
#include <math.h>

// ---------------------------------------------------------------------------
// Problem dims (fixed)
// ---------------------------------------------------------------------------
#define T_TOK 8192
#define H_DIM 2048
#define I_DIM 1408
#define E_NUM 32

#define SZ_W ((size_t)E_NUM * H_DIM * I_DIM)
#define SZ_X ((size_t)T_TOK * H_DIM)
#define SZ_HH ((size_t)T_TOK * I_DIM)

// Scratch (device globals — no allocations allowed anywhere)
__device__ __align__(256) __nv_bfloat16 g_xh[SZ_X];
__device__ __align__(256) __nv_bfloat16 g_xl[SZ_X];
__device__ __align__(256) __nv_bfloat16 g_wgh[SZ_W];
__device__ __align__(256) __nv_bfloat16 g_wgl[SZ_W];
__device__ __align__(256) __nv_bfloat16 g_wuh[SZ_W];
__device__ __align__(256) __nv_bfloat16 g_wul[SZ_W];
__device__ __align__(256) __nv_bfloat16 g_wdh[SZ_W];
__device__ __align__(256) __nv_bfloat16 g_wdl[SZ_W];
__device__ __align__(256) __nv_bfloat16 g_hh[SZ_HH];
__device__ __align__(256) __nv_bfloat16 g_hl[SZ_HH];
__device__ __align__(256) float         g_g32[SZ_HH];   // silu(x@Wg), fp32

// ---------------------------------------------------------------------------
// Base-target (compute_103) PTX helpers: cp.async + ldmatrix + mma.sync
// ---------------------------------------------------------------------------
__device__ __forceinline__ uint32_t smem_u32(const void* p) {
    uint32_t a;
    asm("{ .reg .u64 t; cvta.to.shared.u64 t, %1; cvt.u32.u64 %0, t; }"
        : "=r"(a) : "l"(p));
    return a;
}
__device__ __forceinline__ void cpa16(uint32_t s, const void* g) {
    asm volatile("cp.async.cg.shared.global [%0], [%1], 16;" :: "r"(s), "l"(g));
}
#define CP_COMMIT() asm volatile("cp.async.commit_group;" ::: "memory")
#define CP_WAIT1()  asm volatile("cp.async.wait_group 1;" ::: "memory")

__device__ __forceinline__ void ldsm4(uint32_t* r, uint32_t addr) {
    asm volatile("ldmatrix.sync.aligned.m8n8.x4.shared.b16 {%0,%1,%2,%3}, [%4];"
                 : "=r"(r[0]), "=r"(r[1]), "=r"(r[2]), "=r"(r[3]) : "r"(addr));
}
__device__ __forceinline__ void mma16816(float* d, const uint32_t* a,
                                         uint32_t b0, uint32_t b1) {
    asm volatile(
        "mma.sync.aligned.m16n8k16.row.col.f32.bf16.bf16.f32 "
        "{%0,%1,%2,%3}, {%4,%5,%6,%7}, {%8,%9}, {%0,%1,%2,%3};"
        : "+f"(d[0]), "+f"(d[1]), "+f"(d[2]), "+f"(d[3])
        : "r"(a[0]), "r"(a[1]), "r"(a[2]), "r"(a[3]), "r"(b0), "r"(b1));
}
__device__ __forceinline__ uint32_t pk2(__nv_bfloat16 a, __nv_bfloat16 b) {
    return (uint32_t)__bfloat16_as_ushort(a) | ((uint32_t)__bfloat16_as_ushort(b) << 16);
}

// ---------------------------------------------------------------------------
// Prologue: elementwise fp32 -> bf16 hi/lo split (x)
// ---------------------------------------------------------------------------
__global__ __launch_bounds__(256)
void split_kernel(const float* __restrict__ src,
                  __nv_bfloat16* __restrict__ hi, __nv_bfloat16* __restrict__ lo)
{
    size_t i = ((size_t)blockIdx.x * 256 + threadIdx.x) * 4;
    float4 v = *reinterpret_cast<const float4*>(src + i);
    __nv_bfloat16 h0 = __float2bfloat16(v.x), h1 = __float2bfloat16(v.y);
    __nv_bfloat16 h2 = __float2bfloat16(v.z), h3 = __float2bfloat16(v.w);
    __nv_bfloat16 l0 = __float2bfloat16(v.x - __bfloat162float(h0));
    __nv_bfloat16 l1 = __float2bfloat16(v.y - __bfloat162float(h1));
    __nv_bfloat16 l2 = __float2bfloat16(v.z - __bfloat162float(h2));
    __nv_bfloat16 l3 = __float2bfloat16(v.w - __bfloat16_as_ushort(h3) * 0.0f - __bfloat162float(h3));
    *reinterpret_cast<uint2*>(hi + i) = make_uint2(pk2(h0, h1), pk2(h2, h3));
    *reinterpret_cast<uint2*>(lo + i) = make_uint2(pk2(l0, l1), pk2(l2, l3));
}

// ---------------------------------------------------------------------------
// Prologue: transpose+split weights.  src [Z][K][N] fp32 -> dst [Z][N][K] bf16
// ---------------------------------------------------------------------------
__global__ __launch_bounds__(256)
void trsplit_kernel(const float* __restrict__ src,
                    __nv_bfloat16* __restrict__ hi, __nv_bfloat16* __restrict__ lo,
                    int K, int N)
{
    __shared__ float t[32][33];
    int z  = blockIdx.z;
    int kb = blockIdx.y * 32;
    int nb = blockIdx.x * 32;
    int tx = threadIdx.x, ty = threadIdx.y;   // block (32, 8)
    const float* s = src + (size_t)z * K * N;

    #pragma unroll
    for (int j = ty; j < 32; j += 8)
        t[j][tx] = s[(size_t)(kb + j) * N + nb + tx];
    __syncthreads();

    size_t dbase = (size_t)z * N * K;
    #pragma unroll
    for (int j = ty; j < 32; j += 8) {
        float v = t[tx][j];
        __nv_bfloat16 h = __float2bfloat16(v);
        __nv_bfloat16 l = __float2bfloat16(v - __bfloat162float(h));
        size_t d = dbase + (size_t)(nb + j) * K + kb + tx;
        hi[d] = h;
        lo[d] = l;
    }
}

// ---------------------------------------------------------------------------
// Split-GEMM on mma.sync.  C = Ah*Bh + Al*Bh + Ah*Bl  (fp32 accum)
// A: [M,K] bf16 planes, K-contig.  B: [N,K] bf16 planes, K-contig (= row.col).
// CTA 128x128, BK=64, cp.async double buffer, SW128-style XOR swizzle.
// 8 warps = 4(m) x 2(n); warp tile 32x64; per warp 2x8 m16n8 accum frags.
// EPI: 0 = silu -> g32 ; 1 = h=g32*acc -> hh/hl split ; 2 = -> out fp32
// ---------------------------------------------------------------------------
#define STAGE_B 65536          // 4 planes x 16KB
#define PLANE_B 16384

template<int EPI>
__global__ __launch_bounds__(256, 1)
void gemm_kernel(const __nv_bfloat16* __restrict__ Apl_h,
                 const __nv_bfloat16* __restrict__ Apl_l,
                 const __nv_bfloat16* __restrict__ Bpl_h,
                 const __nv_bfloat16* __restrict__ Bpl_l,
                 const int* __restrict__ offs,
                 int K, int N, int NIT,
                 float* __restrict__ out32)
{
    extern __shared__ char smem[];
    const uint32_t sb = smem_u32(smem);
    const int tid  = threadIdx.x;
    const int wid  = tid >> 5;
    const int lane = tid & 31;
    const int wm   = wid & 3;          // m warp coord (0..3)
    const int wn   = wid >> 2;         // n warp coord (0..1)

    const int m0 = blockIdx.y * 128;
    const int n0 = blockIdx.x * 128;
    int e = 0;
    while (offs[e] <= m0) e++;

    const __nv_bfloat16* Ah = Apl_h + (size_t)m0 * K;
    const __nv_bfloat16* Al = Apl_l + (size_t)m0 * K;
    const size_t wb = (size_t)e * N * K + (size_t)n0 * K;
    const __nv_bfloat16* Bh = Bpl_h + wb;
    const __nv_bfloat16* Bl = Bpl_l + wb;

    // per-thread cp.async chunk coords (4 chunks of 16B per plane)
    // chunk c: row = c>>3, kc = c&7 ; smem off = row*128 + ((kc^(row&7))<<4)
    auto prefetch = [&](int it) {
        const int s = it & 1;
        const int k0 = it * 64;
        uint32_t st = sb + s * STAGE_B;
        #pragma unroll
        for (int p = 0; p < 4; p++) {
            int c   = tid + 256 * p;
            int row = c >> 3;
            int kc  = c & 7;
            uint32_t so = (uint32_t)(row * 128 + ((kc ^ (row & 7)) << 4));
            size_t  go  = (size_t)row * K + k0 + kc * 8;
            cpa16(st + so,               Ah + go);
            cpa16(st + PLANE_B + so,     Al + go);
            cpa16(st + 2 * PLANE_B + so, Bh + go);
            cpa16(st + 3 * PLANE_B + so, Bl + go);
        }
    };

    float acc[2][8][4];
    #pragma unroll
    for (int mf = 0; mf < 2; mf++)
        #pragma unroll
        for (int nf = 0; nf < 8; nf++)
            #pragma unroll
            for (int q = 0; q < 4; q++) acc[mf][nf][q] = 0.f;

    prefetch(0); CP_COMMIT();
    prefetch(1); CP_COMMIT();

    const int l16 = lane & 15;
    const int lhi = lane >> 4;

    for (int it = 0; it < NIT; it++) {
        CP_WAIT1();
        __syncthreads();
        const uint32_t st = sb + (it & 1) * STAGE_B;

        #pragma unroll
        for (int s = 0; s < 4; s++) {
            uint32_t ah[2][4], al[2][4], bh[4][4], bl[4][4];
            #pragma unroll
            for (int mf = 0; mf < 2; mf++) {
                int row = wm * 32 + mf * 16 + l16;
                int ch  = 2 * s + lhi;
                uint32_t off = (uint32_t)(row * 128 + (((ch ^ (row & 7))) << 4));
                ldsm4(ah[mf], st + off);
                ldsm4(al[mf], st + PLANE_B + off);
            }
            #pragma unroll
            for (int nf2 = 0; nf2 < 4; nf2++) {
                int row = wn * 64 + nf2 * 16 + l16;
                int ch  = 2 * s + lhi;
                uint32_t off = (uint32_t)(row * 128 + (((ch ^ (row & 7))) << 4));
                ldsm4(bh[nf2], st + 2 * PLANE_B + off);
                ldsm4(bl[nf2], st + 3 * PLANE_B + off);
            }
            #pragma unroll
            for (int mf = 0; mf < 2; mf++)
                #pragma unroll
                for (int nf = 0; nf < 8; nf++) {
                    const int n2 = nf >> 1, p = nf & 1;
                    mma16816(acc[mf][nf], ah[mf], bh[n2][p], bh[n2][p + 2]);
                    mma16816(acc[mf][nf], al[mf], bh[n2][p], bh[n2][p + 2]);
                    mma16816(acc[mf][nf], ah[mf], bl[n2][p], bl[n2][p + 2]);
                }
        }
        __syncthreads();
        if (it + 2 < NIT) prefetch(it + 2);
        CP_COMMIT();
    }

    // ---- epilogue ----
    const int quad = lane >> 2, tq = lane & 3;
    #pragma unroll
    for (int mf = 0; mf < 2; mf++)
        #pragma unroll
        for (int nf = 0; nf < 8; nf++)
            #pragma unroll
            for (int h = 0; h < 2; h++) {
                int m = m0 + wm * 32 + mf * 16 + quad + h * 8;
                int n = n0 + wn * 64 + nf * 8 + tq * 2;
                float d0 = acc[mf][nf][h * 2 + 0];
                float d1 = acc[mf][nf][h * 2 + 1];
                size_t idx = (size_t)m * N + n;
                if (EPI == 0) {
                    float s0 = d0 / (1.0f + __expf(-d0));
                    float s1 = d1 / (1.0f + __expf(-d1));
                    *reinterpret_cast<float2*>(out32 + idx) = make_float2(s0, s1);
                } else if (EPI == 1) {
                    float2 gv = *reinterpret_cast<const float2*>(g_g32 + idx);
                    float h0 = gv.x * d0, h1 = gv.y * d1;
                    __nv_bfloat16 a0 = __float2bfloat16(h0);
                    __nv_bfloat16 a1 = __float2bfloat16(h1);
                    __nv_bfloat16 b0 = __float2bfloat16(h0 - __bfloat162float(a0));
                    __nv_bfloat16 b1 = __float2bfloat16(h1 - __bfloat162float(a1));
                    *reinterpret_cast<uint32_t*>(g_hh + idx) = pk2(a0, a1);
                    *reinterpret_cast<uint32_t*>(g_hl + idx) = pk2(b0, b1);
                } else {
                    *reinterpret_cast<float2*>(out32 + idx) = make_float2(d0, d1);
                }
            }
}

// ---------------------------------------------------------------------------
extern "C" void kernel_launch(void* const* d_in, const int* in_sizes, int n_in,
                              void* d_out, int out_size)
{
    const float* x    = (const float*)d_in[0];   // [T, H]
    const float* Wg   = (const float*)d_in[1];   // [E, H, I]
    const float* Wu   = (const float*)d_in[2];   // [E, H, I]
    const float* Wd   = (const float*)d_in[3];   // [E, I, H]
    const int*   offs = (const int*)  d_in[4];   // [E]
    float*       out  = (float*)d_out;           // [T, H]

    __nv_bfloat16 *xh, *xl, *wgh, *wgl, *wuh, *wul, *wdh, *wdl, *hh, *hl;
    float *g32;
    cudaGetSymbolAddress((void**)&xh,  g_xh);
    cudaGetSymbolAddress((void**)&xl,  g_xl);
    cudaGetSymbolAddress((void**)&wgh, g_wgh);
    cudaGetSymbolAddress((void**)&wgl, g_wgl);
    cudaGetSymbolAddress((void**)&wuh, g_wuh);
    cudaGetSymbolAddress((void**)&wul, g_wul);
    cudaGetSymbolAddress((void**)&wdh, g_wdh);
    cudaGetSymbolAddress((void**)&wdl, g_wdl);
    cudaGetSymbolAddress((void**)&hh,  g_hh);
    cudaGetSymbolAddress((void**)&hl,  g_hl);
    cudaGetSymbolAddress((void**)&g32, g_g32);

    cudaFuncSetAttribute(gemm_kernel<0>, cudaFuncAttributeMaxDynamicSharedMemorySize, 2 * STAGE_B);
    cudaFuncSetAttribute(gemm_kernel<1>, cudaFuncAttributeMaxDynamicSharedMemorySize, 2 * STAGE_B);
    cudaFuncSetAttribute(gemm_kernel<2>, cudaFuncAttributeMaxDynamicSharedMemorySize, 2 * STAGE_B);

    // Prologue
    split_kernel<<<(int)(SZ_X / 1024), 256>>>(x, xh, xl);
    dim3 tb(32, 8);
    trsplit_kernel<<<dim3(I_DIM / 32, H_DIM / 32, E_NUM), tb>>>(Wg, wgh, wgl, H_DIM, I_DIM);
    trsplit_kernel<<<dim3(I_DIM / 32, H_DIM / 32, E_NUM), tb>>>(Wu, wuh, wul, H_DIM, I_DIM);
    trsplit_kernel<<<dim3(H_DIM / 32, I_DIM / 32, E_NUM), tb>>>(Wd, wdh, wdl, I_DIM, H_DIM);

    // gate: g32 = silu(x @ Wg)
    gemm_kernel<0><<<dim3(I_DIM / 128, T_TOK / 128), 256, 2 * STAGE_B>>>(
        xh, xl, wgh, wgl, offs, H_DIM, I_DIM, H_DIM / 64, g32);
    // up + fuse: h = g32 * (x @ Wu) -> bf16 hi/lo planes
    gemm_kernel<1><<<dim3(I_DIM / 128, T_TOK / 128), 256, 2 * STAGE_B>>>(
        xh, xl, wuh, wul, offs, H_DIM, I_DIM, H_DIM / 64, nullptr);
    // down: out = h @ Wd
    gemm_kernel<2><<<dim3(H_DIM / 128, T_TOK / 128), 256, 2 * STAGE_B>>>(
        hh, hl, wdh, wdl, offs, I_DIM, H_DIM, I_DIM / 64, out);
}

// round 4
// speedup vs baseline: 4.5136x; 2.6928x over previous
#include <cuda_runtime.h>
#include <cuda_fp16.h>
#include <cstdint>
#include <math.h>

// ---------------------------------------------------------------------------
// Problem dims (fixed)
// ---------------------------------------------------------------------------
#define T_TOK 8192
#define H_DIM 2048
#define I_DIM 1408
#define E_NUM 32

#define SZ_W ((size_t)E_NUM * H_DIM * I_DIM)
#define SZ_X ((size_t)T_TOK * H_DIM)
#define SZ_HH ((size_t)T_TOK * I_DIM)

// Scratch (device globals — no allocations allowed anywhere).
// All tensors keep their NATIVE layout; weights are [E][K][N] n-contig.
__device__ __align__(256) __half g_x16[SZ_X];    // [T][H]
__device__ __align__(256) __half g_wg16[SZ_W];   // [E][H][I]
__device__ __align__(256) __half g_wu16[SZ_W];   // [E][H][I]
__device__ __align__(256) __half g_wd16[SZ_W];   // [E][I][H]
__device__ __align__(256) __half g_h16[SZ_HH];   // [T][I]

// ---------------------------------------------------------------------------
// PTX helpers (base-target legal: cp.async / ldmatrix / mma.sync, sm_80+)
// ---------------------------------------------------------------------------
__device__ __forceinline__ uint32_t smem_u32(const void* p) {
    uint32_t a;
    asm("{ .reg .u64 t; cvta.to.shared.u64 t, %1; cvt.u32.u64 %0, t; }"
        : "=r"(a) : "l"(p));
    return a;
}
__device__ __forceinline__ void cpa16(uint32_t s, const void* g) {
    asm volatile("cp.async.cg.shared.global [%0], [%1], 16;" :: "r"(s), "l"(g));
}
#define CP_COMMIT() asm volatile("cp.async.commit_group;" ::: "memory")
#define CP_WAIT1()  asm volatile("cp.async.wait_group 1;" ::: "memory")

__device__ __forceinline__ void ldsm4(uint32_t* r, uint32_t addr) {
    asm volatile("ldmatrix.sync.aligned.m8n8.x4.shared.b16 {%0,%1,%2,%3}, [%4];"
                 : "=r"(r[0]), "=r"(r[1]), "=r"(r[2]), "=r"(r[3]) : "r"(addr));
}
__device__ __forceinline__ void ldsm4t(uint32_t* r, uint32_t addr) {
    asm volatile("ldmatrix.sync.aligned.m8n8.x4.trans.shared.b16 {%0,%1,%2,%3}, [%4];"
                 : "=r"(r[0]), "=r"(r[1]), "=r"(r[2]), "=r"(r[3]) : "r"(addr));
}
__device__ __forceinline__ void mma16816(float* d, const uint32_t* a,
                                         uint32_t b0, uint32_t b1) {
    asm volatile(
        "mma.sync.aligned.m16n8k16.row.col.f32.f16.f16.f32 "
        "{%0,%1,%2,%3}, {%4,%5,%6,%7}, {%8,%9}, {%0,%1,%2,%3};"
        : "+f"(d[0]), "+f"(d[1]), "+f"(d[2]), "+f"(d[3])
        : "r"(a[0]), "r"(a[1]), "r"(a[2]), "r"(a[3]), "r"(b0), "r"(b1));
}
__device__ __forceinline__ uint32_t pkh2(float a, float b) {
    __half2 h = __floats2half2_rn(a, b);
    return *reinterpret_cast<uint32_t*>(&h);
}

// ---------------------------------------------------------------------------
// Prologue: streaming fp32 -> fp16 convert (layout-preserving, HBM-bound)
// ---------------------------------------------------------------------------
__global__ __launch_bounds__(256)
void cvt_kernel(const float* __restrict__ src, __half* __restrict__ dst)
{
    size_t i = ((size_t)blockIdx.x * 256 + threadIdx.x) * 8;
    float4 v0 = *reinterpret_cast<const float4*>(src + i);
    float4 v1 = *reinterpret_cast<const float4*>(src + i + 4);
    uint4 o;
    o.x = pkh2(v0.x, v0.y);
    o.y = pkh2(v0.z, v0.w);
    o.z = pkh2(v1.x, v1.y);
    o.w = pkh2(v1.z, v1.w);
    *reinterpret_cast<uint4*>(dst + i) = o;
}

// ---------------------------------------------------------------------------
// GEMM cores.
// A: [M,K] fp16 K-contig.  B: [K,N] fp16 n-contig (native weight layout).
// CTA 128x128, BK=64, cp.async double buffer.
// A tile  : [128 m][64 k]  rows of 128B, SW128 xor swizzle (proven R3).
// B tiles : [64 k][128 n]  = two 64-n halves, each [64 k rows][128B], SW128.
// B fragments via ldmatrix.x4.trans (trans of [K][N] == non-trans of [N][K]).
// 8 warps = 4(m) x 2(n); warp tile 32x64; 2x8 m16n8 accum frags per matrix.
// ---------------------------------------------------------------------------
#define APLANE 16384
#define BPLANE 16384

__device__ __forceinline__ void prefetch_a(const __half* A, int K, int k0,
                                           uint32_t st, int tid) {
    #pragma unroll
    for (int p = 0; p < 4; p++) {
        int c   = tid + 256 * p;          // 0..1023
        int row = c >> 3;                 // m 0..127
        int kc  = c & 7;
        uint32_t so = (uint32_t)(row * 128 + ((kc ^ (row & 7)) << 4));
        cpa16(st + so, A + (size_t)row * K + k0 + kc * 8);
    }
}
__device__ __forceinline__ void prefetch_b(const __half* B, int N, int k0,
                                           int n0, uint32_t st, int tid) {
    #pragma unroll
    for (int p = 0; p < 4; p++) {
        int c    = tid + 256 * p;         // 0..1023
        int row  = c >> 4;                // k 0..63
        int j    = c & 15;                // 16B chunk in 256B of n
        int half = j >> 3;
        int jj   = j & 7;
        uint32_t so = (uint32_t)(half * 8192 + row * 128 + ((jj ^ (row & 7)) << 4));
        cpa16(st + so, B + (size_t)(k0 + row) * N + n0 + j * 8);
    }
}

// B fragment smem offset for k16-step s, 16-wide n subtile nf2, this lane.
__device__ __forceinline__ uint32_t b_off(int s, int base_n, int lane) {
    int kRow = s * 16 + (lane & 7) + ((lane >> 4) << 3);
    int nOff = base_n + (((lane >> 3) & 1) << 3);
    int half = nOff >> 6;
    int jj   = (nOff & 63) >> 3;
    return (uint32_t)(half * 8192 + kRow * 128 + ((jj ^ (kRow & 7)) << 4));
}

// ---------------------------------------------------------------------------
// GEMM1: fused gate+up.  g = x@Wg, u = x@Wu, h = silu(g)*u -> fp16 [T][I]
// ---------------------------------------------------------------------------
#define STG1 (APLANE + 2 * BPLANE)    // 48 KB per stage

__global__ __launch_bounds__(256, 1)
void gemm1_kernel(const int* __restrict__ offs)
{
    extern __shared__ char smem[];
    const uint32_t sb = smem_u32(smem);
    const int tid  = threadIdx.x;
    const int wid  = tid >> 5;
    const int lane = tid & 31;
    const int wm   = wid & 3;
    const int wn   = wid >> 2;

    const int m0 = blockIdx.y * 128;
    const int n0 = blockIdx.x * 128;
    int e = 0;
    while (offs[e] <= m0) e++;

    const __half* A  = g_x16 + (size_t)m0 * H_DIM;
    const __half* Bg = g_wg16 + (size_t)e * H_DIM * I_DIM;
    const __half* Bu = g_wu16 + (size_t)e * H_DIM * I_DIM;

    auto prefetch = [&](int it) {
        uint32_t st = sb + (it & 1) * STG1;
        int k0 = it * 64;
        prefetch_a(A, H_DIM, k0, st, tid);
        prefetch_b(Bg, I_DIM, k0, n0, st + APLANE, tid);
        prefetch_b(Bu, I_DIM, k0, n0, st + APLANE + BPLANE, tid);
    };

    float accg[2][8][4], accu[2][8][4];
    #pragma unroll
    for (int mf = 0; mf < 2; mf++)
        #pragma unroll
        for (int nf = 0; nf < 8; nf++)
            #pragma unroll
            for (int q = 0; q < 4; q++) { accg[mf][nf][q] = 0.f; accu[mf][nf][q] = 0.f; }

    prefetch(0); CP_COMMIT();
    prefetch(1); CP_COMMIT();

    const int l16 = lane & 15;
    const int lhi = lane >> 4;
    const int NIT = H_DIM / 64;   // 32

    for (int it = 0; it < NIT; it++) {
        CP_WAIT1();
        __syncthreads();
        const uint32_t st = sb + (it & 1) * STG1;

        #pragma unroll
        for (int s = 0; s < 4; s++) {
            uint32_t a[2][4], bg[4][4], bu[4][4];
            #pragma unroll
            for (int mf = 0; mf < 2; mf++) {
                int row = wm * 32 + mf * 16 + l16;
                int ch  = 2 * s + lhi;
                ldsm4(a[mf], st + (uint32_t)(row * 128 + ((ch ^ (row & 7)) << 4)));
            }
            #pragma unroll
            for (int nf2 = 0; nf2 < 4; nf2++) {
                uint32_t off = b_off(s, wn * 64 + nf2 * 16, lane);
                ldsm4t(bg[nf2], st + APLANE + off);
                ldsm4t(bu[nf2], st + APLANE + BPLANE + off);
            }
            #pragma unroll
            for (int mf = 0; mf < 2; mf++)
                #pragma unroll
                for (int nf = 0; nf < 8; nf++) {
                    const int n2 = nf >> 1, p = nf & 1;
                    mma16816(accg[mf][nf], a[mf], bg[n2][p], bg[n2][p + 2]);
                    mma16816(accu[mf][nf], a[mf], bu[n2][p], bu[n2][p + 2]);
                }
        }
        __syncthreads();
        if (it + 2 < NIT) prefetch(it + 2);
        CP_COMMIT();
    }

    // Epilogue: h = silu(g) * u -> fp16
    const int quad = lane >> 2, tq = lane & 3;
    #pragma unroll
    for (int mf = 0; mf < 2; mf++)
        #pragma unroll
        for (int nf = 0; nf < 8; nf++)
            #pragma unroll
            for (int h = 0; h < 2; h++) {
                int m = m0 + wm * 32 + mf * 16 + quad + h * 8;
                int n = n0 + wn * 64 + nf * 8 + tq * 2;
                float g0 = accg[mf][nf][h * 2 + 0], u0 = accu[mf][nf][h * 2 + 0];
                float g1 = accg[mf][nf][h * 2 + 1], u1 = accu[mf][nf][h * 2 + 1];
                float h0 = (g0 / (1.0f + __expf(-g0))) * u0;
                float h1 = (g1 / (1.0f + __expf(-g1))) * u1;
                *reinterpret_cast<uint32_t*>(g_h16 + (size_t)m * I_DIM + n) = pkh2(h0, h1);
            }
}

// ---------------------------------------------------------------------------
// GEMM2: down proj.  out = h @ Wd -> fp32
// ---------------------------------------------------------------------------
#define STG2 (APLANE + BPLANE)        // 32 KB per stage

__global__ __launch_bounds__(256, 1)
void gemm2_kernel(const int* __restrict__ offs, float* __restrict__ out)
{
    extern __shared__ char smem[];
    const uint32_t sb = smem_u32(smem);
    const int tid  = threadIdx.x;
    const int wid  = tid >> 5;
    const int lane = tid & 31;
    const int wm   = wid & 3;
    const int wn   = wid >> 2;

    const int m0 = blockIdx.y * 128;
    const int n0 = blockIdx.x * 128;
    int e = 0;
    while (offs[e] <= m0) e++;

    const __half* A = g_h16 + (size_t)m0 * I_DIM;
    const __half* B = g_wd16 + (size_t)e * I_DIM * H_DIM;

    auto prefetch = [&](int it) {
        uint32_t st = sb + (it & 1) * STG2;
        int k0 = it * 64;
        prefetch_a(A, I_DIM, k0, st, tid);
        prefetch_b(B, H_DIM, k0, n0, st + APLANE, tid);
    };

    float acc[2][8][4];
    #pragma unroll
    for (int mf = 0; mf < 2; mf++)
        #pragma unroll
        for (int nf = 0; nf < 8; nf++)
            #pragma unroll
            for (int q = 0; q < 4; q++) acc[mf][nf][q] = 0.f;

    prefetch(0); CP_COMMIT();
    prefetch(1); CP_COMMIT();

    const int l16 = lane & 15;
    const int lhi = lane >> 4;
    const int NIT = I_DIM / 64;   // 22

    for (int it = 0; it < NIT; it++) {
        CP_WAIT1();
        __syncthreads();
        const uint32_t st = sb + (it & 1) * STG2;

        #pragma unroll
        for (int s = 0; s < 4; s++) {
            uint32_t a[2][4], b[4][4];
            #pragma unroll
            for (int mf = 0; mf < 2; mf++) {
                int row = wm * 32 + mf * 16 + l16;
                int ch  = 2 * s + lhi;
                ldsm4(a[mf], st + (uint32_t)(row * 128 + ((ch ^ (row & 7)) << 4)));
            }
            #pragma unroll
            for (int nf2 = 0; nf2 < 4; nf2++)
                ldsm4t(b[nf2], st + APLANE + b_off(s, wn * 64 + nf2 * 16, lane));
            #pragma unroll
            for (int mf = 0; mf < 2; mf++)
                #pragma unroll
                for (int nf = 0; nf < 8; nf++) {
                    const int n2 = nf >> 1, p = nf & 1;
                    mma16816(acc[mf][nf], a[mf], b[n2][p], b[n2][p + 2]);
                }
        }
        __syncthreads();
        if (it + 2 < NIT) prefetch(it + 2);
        CP_COMMIT();
    }

    const int quad = lane >> 2, tq = lane & 3;
    #pragma unroll
    for (int mf = 0; mf < 2; mf++)
        #pragma unroll
        for (int nf = 0; nf < 8; nf++)
            #pragma unroll
            for (int h = 0; h < 2; h++) {
                int m = m0 + wm * 32 + mf * 16 + quad + h * 8;
                int n = n0 + wn * 64 + nf * 8 + tq * 2;
                *reinterpret_cast<float2*>(out + (size_t)m * H_DIM + n) =
                    make_float2(acc[mf][nf][h * 2 + 0], acc[mf][nf][h * 2 + 1]);
            }
}

// ---------------------------------------------------------------------------
extern "C" void kernel_launch(void* const* d_in, const int* in_sizes, int n_in,
                              void* d_out, int out_size)
{
    const float* x    = (const float*)d_in[0];   // [T, H]
    const float* Wg   = (const float*)d_in[1];   // [E, H, I]
    const float* Wu   = (const float*)d_in[2];   // [E, H, I]
    const float* Wd   = (const float*)d_in[3];   // [E, I, H]
    const int*   offs = (const int*)  d_in[4];   // [E]
    float*       out  = (float*)d_out;           // [T, H]

    __half *x16, *wg16, *wu16, *wd16;
    cudaGetSymbolAddress((void**)&x16,  g_x16);
    cudaGetSymbolAddress((void**)&wg16, g_wg16);
    cudaGetSymbolAddress((void**)&wu16, g_wu16);
    cudaGetSymbolAddress((void**)&wd16, g_wd16);

    cudaFuncSetAttribute(gemm1_kernel, cudaFuncAttributeMaxDynamicSharedMemorySize, 2 * STG1);
    cudaFuncSetAttribute(gemm2_kernel, cudaFuncAttributeMaxDynamicSharedMemorySize, 2 * STG2);

    // Prologue: streaming fp32 -> fp16 (layout preserved, no transpose)
    cvt_kernel<<<(int)(SZ_X / 2048), 256>>>(x,  x16);
    cvt_kernel<<<(int)(SZ_W / 2048), 256>>>(Wg, wg16);
    cvt_kernel<<<(int)(SZ_W / 2048), 256>>>(Wu, wu16);
    cvt_kernel<<<(int)(SZ_W / 2048), 256>>>(Wd, wd16);

    // Fused gate+up (+silu, h -> fp16), then down proj
    gemm1_kernel<<<dim3(I_DIM / 128, T_TOK / 128), 256, 2 * STG1>>>(offs);
    gemm2_kernel<<<dim3(H_DIM / 128, T_TOK / 128), 256, 2 * STG2>>>(offs, out);
}